// round 10
// baseline (speedup 1.0000x reference)
#include <cuda_runtime.h>
#include <stdint.h>

// Problem constants
#define NUM_COORDS   200000
#define FEAT_C       128
#define MAX_SELECTED 262144
#define N_ELEMS      (512 * NUM_COORDS)         // 102,400,000 mask elements
#define THREADS      256
#define ELEMS_PER_TH 32
#define ELEMS_PER_BLK (THREADS * ELEMS_PER_TH)  // 8192
#define NBLK         (N_ELEMS / ELEMS_PER_BLK)  // 12500 exactly

// Decoupled-lookback descriptor: bits 31:30 flag, bits 29:0 value.
#define FLAG_INVALID 0u
#define FLAG_AGG     (1u << 30)
#define FLAG_PREFIX  (2u << 30)
#define VAL_MASK     0x3FFFFFFFu

// Scratch. g_desc starts zero (INVALID); k_gather resets it after every fused
// run so each graph replay sees a clean state.
__device__ unsigned g_desc[NBLK];
__device__ int g_count;
__device__ int g_selidx[MAX_SELECTED];
__device__ unsigned g_nonconform = 0;  // 1 => byte-bools; 0 => 32-bit elems

// Relaxed GPU-scope load/store: descriptor word is self-contained, so no
// ordering needed. Plain L2 loads avoid the atomic-ALU serialization that
// made polling the bottleneck in R9.
__device__ __forceinline__ unsigned ld_desc(int idx) {
    unsigned v;
    asm volatile("ld.relaxed.gpu.b32 %0, [%1];" : "=r"(v) : "l"(&g_desc[idx]));
    return v;
}
__device__ __forceinline__ void st_desc(int idx, unsigned v) {
    asm volatile("st.relaxed.gpu.b32 [%0], %1;" :: "l"(&g_desc[idx]), "r"(v) : "memory");
}

// ---------------------------------------------------------------------------
// Mode detection (256K-word scan). Word-mode masks contain only
// {0,1,0x3F800000}. Monotone + input-determined => replay-safe without reset.
// ---------------------------------------------------------------------------
__global__ void k_detect(const unsigned* __restrict__ w) {
    unsigned i = blockIdx.x * blockDim.x + threadIdx.x;
    unsigned bad = 0;
    for (unsigned j = i; j < (1u << 18); j += gridDim.x * blockDim.x) {
        unsigned v = w[j];
        if (v != 0u && v != 1u && v != 0x3F800000u) bad = 1u;
    }
    if (bad) g_nonconform = 1u;
}

// Load this thread's 32 contiguous elements; return count of set elements.
__device__ __forceinline__ int load_count(const void* mask, int blk, int tid,
                                          int byte_mode, uint4 v[8]) {
    if (byte_mode) {
        const uint4* p = (const uint4*)mask + (size_t)blk * 512 + (size_t)tid * 2;
        unsigned a = 0;
#pragma unroll
        for (int i = 0; i < 2; i++) {
            v[i] = p[i];
            a = __dp4a(v[i].x, 0x01010101u, a);
            a = __dp4a(v[i].y, 0x01010101u, a);
            a = __dp4a(v[i].z, 0x01010101u, a);
            a = __dp4a(v[i].w, 0x01010101u, a);
        }
        return (int)a;
    } else {
        const uint4* p = (const uint4*)mask + (size_t)blk * 2048 + (size_t)tid * 8;
        int c = 0;
#pragma unroll
        for (int i = 0; i < 8; i++) {
            v[i] = p[i];
            c += (v[i].x != 0u) + (v[i].y != 0u) + (v[i].z != 0u) + (v[i].w != 0u);
        }
        return c;
    }
}

// ---------------------------------------------------------------------------
// Fused single-pass: block scan + WARP-wide decoupled lookback (relaxed-load
// polling) + ordered light emit (ext coords as float values + selidx).
// ---------------------------------------------------------------------------
__global__ void k_fused(const void* __restrict__ mask,
                        const int4* __restrict__ coords,
                        float4* __restrict__ out_ext) {
    const int blk = blockIdx.x, tid = threadIdx.x;
    const int lane = tid & 31, wrp = tid >> 5;
    const int byte_mode = (g_nonconform != 0u);

    uint4 v[8];
    int cnt = load_count(mask, blk, tid, byte_mode, v);

    // warp inclusive scan of per-thread counts
    int incl = cnt;
#pragma unroll
    for (int o = 1; o < 32; o <<= 1) {
        int t = __shfl_up_sync(0xFFFFFFFFu, incl, o);
        if (lane >= o) incl += t;
    }
    __shared__ int ws[8];
    __shared__ int s_excl;
    if (lane == 31) ws[wrp] = incl;
    __syncthreads();

    int wbase = 0, total = 0;
#pragma unroll
    for (int i = 0; i < 8; i++) {
        int w = ws[i];
        wbase += (i < wrp) ? w : 0;
        total += w;
    }

    // Publish this block's status
    if (tid == 0) {
        if (blk == 0) {
            st_desc(0, FLAG_PREFIX | (unsigned)total);
            s_excl = 0;
            if (blk == NBLK - 1) g_count = total;
        } else {
            st_desc(blk, FLAG_AGG | (unsigned)total);
        }
    }

    // Warp 0 lookback: 32 descriptors per window, relaxed-load polling.
    // Sentinel (32) == window size: all-AGG windows consume exactly 32.
    if (wrp == 0 && blk > 0) {
        int excl = 0;
        int k = blk - 1;
        while (true) {
            int idx = k - lane;
            unsigned s = (idx >= 0) ? ld_desc(idx) : (FLAG_PREFIX | 0u);
            unsigned flag = s & 0xC0000000u;
            unsigned val  = s & VAL_MASK;
            unsigned bP = __ballot_sync(0xFFFFFFFFu, flag == FLAG_PREFIX);
            unsigned bI = __ballot_sync(0xFFFFFFFFu, flag == FLAG_INVALID);
            int firstP = bP ? (__ffs(bP) - 1) : 32;
            int firstI = bI ? (__ffs(bI) - 1) : 32;

            if (firstP < firstI) {
                unsigned contrib = (lane <= firstP) ? val : 0u;
#pragma unroll
                for (int o = 16; o; o >>= 1)
                    contrib += __shfl_xor_sync(0xFFFFFFFFu, contrib, o);
                excl += (int)contrib;
                break;
            } else if (firstI > 0) {
                unsigned contrib = (lane < firstI) ? val : 0u;
#pragma unroll
                for (int o = 16; o; o >>= 1)
                    contrib += __shfl_xor_sync(0xFFFFFFFFu, contrib, o);
                excl += (int)contrib;
                k -= firstI;
            } else {
                __nanosleep(40);
            }
        }
        if (lane == 0) {
            s_excl = excl;
            st_desc(blk, FLAG_PREFIX | (unsigned)(excl + total));
            if (blk == NBLK - 1) g_count = excl + total;
        }
    }
    __syncthreads();

    int pout = s_excl + wbase + (incl - cnt);
    const int ebase = blk * ELEMS_PER_BLK + tid * ELEMS_PER_TH;

    auto emit_one = [&](int elem) {
        if (pout < MAX_SELECTED) {
            int coord = elem % NUM_COORDS;
            int box   = elem / NUM_COORDS;
            g_selidx[pout] = coord;
            int4 c = coords[coord];
            out_ext[pout] = make_float4((float)c.x, (float)c.y,
                                        (float)c.z, (float)box);
        }
        pout++;
    };

    if (byte_mode) {
#pragma unroll
        for (int i = 0; i < 2; i++) {
            unsigned words[4] = { v[i].x, v[i].y, v[i].z, v[i].w };
#pragma unroll
            for (int j = 0; j < 4; j++) {
                unsigned w32 = words[j];
                if (w32 == 0u) continue;
#pragma unroll
                for (int b = 0; b < 4; b++)
                    if ((w32 >> (8 * b)) & 0xFFu)
                        emit_one(ebase + i * 16 + j * 4 + b);
            }
        }
    } else {
#pragma unroll
        for (int i = 0; i < 8; i++) {
            unsigned words[4] = { v[i].x, v[i].y, v[i].z, v[i].w };
#pragma unroll
            for (int j = 0; j < 4; j++)
                if (words[j] != 0u) emit_one(ebase + i * 4 + j);
        }
    }
}

// ---------------------------------------------------------------------------
// Gather: warp-per-row feature copy + zero tail. Also resets g_desc for the
// next graph replay (safe: stream-ordered after k_fused).
// ---------------------------------------------------------------------------
__global__ void k_gather(const float4* __restrict__ feat,
                         float4* __restrict__ out_ext,
                         float4* __restrict__ out_feat) {
    const int gt = blockIdx.x * blockDim.x + threadIdx.x;
    if (gt < NBLK) g_desc[gt] = FLAG_INVALID;

    const int gw   = gt >> 5;
    const int lane = threadIdx.x & 31;
    if (gw >= MAX_SELECTED) return;
    if (gw < g_count) {
        int c = g_selidx[gw];
        out_feat[(size_t)gw * 32 + lane] = feat[(size_t)c * 32 + lane];
    } else {
        out_feat[(size_t)gw * 32 + lane] = make_float4(0.f, 0.f, 0.f, 0.f);
        if (lane == 0) out_ext[gw] = make_float4(0.f, 0.f, 0.f, 0.f);
    }
}

// ---------------------------------------------------------------------------
extern "C" void kernel_launch(void* const* d_in, const int* in_sizes, int n_in,
                              void* d_out, int out_size) {
    const int4*   coords = nullptr;
    const float4* feat   = nullptr;
    const void*   mask   = nullptr;
    for (int i = 0; i < n_in; i++) {
        if (in_sizes[i] == NUM_COORDS * 4)           coords = (const int4*)d_in[i];
        else if (in_sizes[i] == NUM_COORDS * FEAT_C) feat   = (const float4*)d_in[i];
        else if (in_sizes[i] == N_ELEMS)             mask   = d_in[i];
    }
    (void)out_size;

    float* out = (float*)d_out;
    float4* out_ext  = (float4*)out;                              // [262144,4] as floats
    float4* out_feat = (float4*)(out + 4 * (size_t)MAX_SELECTED); // [262144,128]

    k_detect<<<512, 256>>>((const unsigned*)mask);
    k_fused<<<NBLK, THREADS>>>(mask, coords, out_ext);
    k_gather<<<MAX_SELECTED * 32 / 256, 256>>>(feat, out_ext, out_feat);
}

// round 11
// speedup vs baseline: 1.7733x; 1.7733x over previous
#include <cuda_runtime.h>
#include <stdint.h>

// Problem constants
#define NUM_COORDS   200000
#define FEAT_C       128
#define MAX_SELECTED 262144
#define N_ELEMS      (512 * NUM_COORDS)         // 102,400,000 mask elements
#define THREADS      512
#define ELEMS_PER_TH 16
#define ELEMS_PER_BLK (THREADS * ELEMS_PER_TH)  // 8192
#define NBLK         (N_ELEMS / ELEMS_PER_BLK)  // 12500 exactly
#define NWARP        (THREADS / 32)             // 16

// Decoupled-lookback descriptor: bits 31:30 flag, bits 29:0 value.
#define FLAG_INVALID 0u
#define FLAG_AGG     (1u << 30)
#define FLAG_PREFIX  (2u << 30)
#define VAL_MASK     0x3FFFFFFFu

// Scratch. g_desc starts zero (INVALID); k_gather resets it after every fused
// run so each graph replay sees a clean state.
__device__ unsigned g_desc[NBLK];
__device__ int g_count;
__device__ int g_selidx[MAX_SELECTED];
__device__ unsigned g_nonconform = 0;  // 1 => byte-bools; 0 => 32-bit elems

// ---------------------------------------------------------------------------
// Mode detection (256K-word scan). Word-mode masks contain only
// {0,1,0x3F800000}. Monotone + input-determined => replay-safe without reset.
// ---------------------------------------------------------------------------
__global__ void k_detect(const unsigned* __restrict__ w) {
    unsigned i = blockIdx.x * blockDim.x + threadIdx.x;
    unsigned bad = 0;
    for (unsigned j = i; j < (1u << 18); j += gridDim.x * blockDim.x) {
        unsigned v = w[j];
        if (v != 0u && v != 1u && v != 0x3F800000u) bad = 1u;
    }
    if (bad) g_nonconform = 1u;
}

// Load this thread's 16 contiguous elements; return count of set elements.
// (16 elems/thread keeps tile data at 4 x uint4 = 16 regs, as in the proven
// R6 configuration.)
__device__ __forceinline__ int load_count(const void* mask, int blk, int tid,
                                          int byte_mode, uint4 v[4]) {
    if (byte_mode) {
        v[0] = ((const uint4*)mask)[(size_t)blk * (ELEMS_PER_BLK / 16) + tid];
        unsigned a = 0;
        a = __dp4a(v[0].x, 0x01010101u, a);
        a = __dp4a(v[0].y, 0x01010101u, a);
        a = __dp4a(v[0].z, 0x01010101u, a);
        a = __dp4a(v[0].w, 0x01010101u, a);
        return (int)a;
    } else {
        const uint4* p = (const uint4*)mask + (size_t)blk * (ELEMS_PER_BLK / 4)
                         + (size_t)tid * 4;
        int c = 0;
#pragma unroll
        for (int i = 0; i < 4; i++) {
            v[i] = p[i];
            c += (v[i].x != 0u) + (v[i].y != 0u) + (v[i].z != 0u) + (v[i].w != 0u);
        }
        return c;
    }
}

// ---------------------------------------------------------------------------
// Fused single-pass: block scan + warp-0 decoupled lookback (atomicAdd
// polling — the proven R6 mechanism) + ordered light emit.
// Only change vs R6: 512-thread blocks => tile 8192, NBLK 12500.
// ---------------------------------------------------------------------------
__global__ void __launch_bounds__(THREADS)
k_fused(const void* __restrict__ mask,
        const int4* __restrict__ coords,
        float4* __restrict__ out_ext) {
    const int blk = blockIdx.x, tid = threadIdx.x;
    const int lane = tid & 31, wrp = tid >> 5;
    const int byte_mode = (g_nonconform != 0u);

    uint4 v[4];
    int cnt = load_count(mask, blk, tid, byte_mode, v);

    // warp inclusive scan of per-thread counts
    int incl = cnt;
#pragma unroll
    for (int o = 1; o < 32; o <<= 1) {
        int t = __shfl_up_sync(0xFFFFFFFFu, incl, o);
        if (lane >= o) incl += t;
    }
    __shared__ int ws[NWARP];
    __shared__ int s_excl;
    if (lane == 31) ws[wrp] = incl;
    __syncthreads();

    int wbase = 0, total = 0;
#pragma unroll
    for (int i = 0; i < NWARP; i++) {
        int w = ws[i];
        wbase += (i < wrp) ? w : 0;
        total += w;
    }

    // Publish this block's status
    if (tid == 0) {
        if (blk == 0) {
            atomicExch(&g_desc[0], FLAG_PREFIX | (unsigned)total);
            s_excl = 0;
            if (blk == NBLK - 1) g_count = total;
        } else {
            atomicExch(&g_desc[blk], FLAG_AGG | (unsigned)total);
        }
    }

    // Warp 0 lookback: 32-descriptor window, atomicAdd polling (R6-proven).
    // Sentinel (32) == window size.
    if (wrp == 0 && blk > 0) {
        int excl = 0;
        int k = blk - 1;
        while (true) {
            int idx = k - lane;
            unsigned s = (idx >= 0) ? atomicAdd(&g_desc[idx], 0u)
                                    : (FLAG_PREFIX | 0u);
            unsigned flag = s & 0xC0000000u;
            unsigned val  = s & VAL_MASK;
            unsigned bP = __ballot_sync(0xFFFFFFFFu, flag == FLAG_PREFIX);
            unsigned bI = __ballot_sync(0xFFFFFFFFu, flag == FLAG_INVALID);
            int firstP = bP ? (__ffs(bP) - 1) : 32;
            int firstI = bI ? (__ffs(bI) - 1) : 32;

            if (firstP < firstI) {
                unsigned contrib = (lane <= firstP) ? val : 0u;
#pragma unroll
                for (int o = 16; o; o >>= 1)
                    contrib += __shfl_xor_sync(0xFFFFFFFFu, contrib, o);
                excl += (int)contrib;
                break;
            } else if (firstI > 0) {
                unsigned contrib = (lane < firstI) ? val : 0u;
#pragma unroll
                for (int o = 16; o; o >>= 1)
                    contrib += __shfl_xor_sync(0xFFFFFFFFu, contrib, o);
                excl += (int)contrib;
                k -= firstI;
            } else {
                __nanosleep(60);
            }
        }
        if (lane == 0) {
            s_excl = excl;
            atomicExch(&g_desc[blk], FLAG_PREFIX | (unsigned)(excl + total));
            if (blk == NBLK - 1) g_count = excl + total;
        }
    }
    __syncthreads();

    int pout = s_excl + wbase + (incl - cnt);
    const int ebase = blk * ELEMS_PER_BLK + tid * ELEMS_PER_TH;

    auto emit_one = [&](int elem) {
        if (pout < MAX_SELECTED) {
            int coord = elem % NUM_COORDS;
            int box   = elem / NUM_COORDS;
            g_selidx[pout] = coord;
            int4 c = coords[coord];
            out_ext[pout] = make_float4((float)c.x, (float)c.y,
                                        (float)c.z, (float)box);
        }
        pout++;
    };

    if (byte_mode) {
        unsigned words[4] = { v[0].x, v[0].y, v[0].z, v[0].w };
#pragma unroll
        for (int j = 0; j < 4; j++) {
            unsigned w32 = words[j];
            if (w32 == 0u) continue;
#pragma unroll
            for (int b = 0; b < 4; b++)
                if ((w32 >> (8 * b)) & 0xFFu) emit_one(ebase + j * 4 + b);
        }
    } else {
#pragma unroll
        for (int i = 0; i < 4; i++) {
            unsigned words[4] = { v[i].x, v[i].y, v[i].z, v[i].w };
#pragma unroll
            for (int j = 0; j < 4; j++)
                if (words[j] != 0u) emit_one(ebase + i * 4 + j);
        }
    }
}

// ---------------------------------------------------------------------------
// Gather: warp-per-row feature copy + zero tail. Also resets g_desc for the
// next graph replay (safe: stream-ordered after k_fused).
// ---------------------------------------------------------------------------
__global__ void k_gather(const float4* __restrict__ feat,
                         float4* __restrict__ out_ext,
                         float4* __restrict__ out_feat) {
    const int gt = blockIdx.x * blockDim.x + threadIdx.x;
    if (gt < NBLK) g_desc[gt] = FLAG_INVALID;

    const int gw   = gt >> 5;
    const int lane = threadIdx.x & 31;
    if (gw >= MAX_SELECTED) return;
    if (gw < g_count) {
        int c = g_selidx[gw];
        out_feat[(size_t)gw * 32 + lane] = feat[(size_t)c * 32 + lane];
    } else {
        out_feat[(size_t)gw * 32 + lane] = make_float4(0.f, 0.f, 0.f, 0.f);
        if (lane == 0) out_ext[gw] = make_float4(0.f, 0.f, 0.f, 0.f);
    }
}

// ---------------------------------------------------------------------------
extern "C" void kernel_launch(void* const* d_in, const int* in_sizes, int n_in,
                              void* d_out, int out_size) {
    const int4*   coords = nullptr;
    const float4* feat   = nullptr;
    const void*   mask   = nullptr;
    for (int i = 0; i < n_in; i++) {
        if (in_sizes[i] == NUM_COORDS * 4)           coords = (const int4*)d_in[i];
        else if (in_sizes[i] == NUM_COORDS * FEAT_C) feat   = (const float4*)d_in[i];
        else if (in_sizes[i] == N_ELEMS)             mask   = d_in[i];
    }
    (void)out_size;

    float* out = (float*)d_out;
    float4* out_ext  = (float4*)out;                              // [262144,4] as floats
    float4* out_feat = (float4*)(out + 4 * (size_t)MAX_SELECTED); // [262144,128]

    k_detect<<<512, 256>>>((const unsigned*)mask);
    k_fused<<<NBLK, THREADS>>>(mask, coords, out_ext);
    k_gather<<<MAX_SELECTED * 32 / 256, 256>>>(feat, out_ext, out_feat);
}